// round 7
// baseline (speedup 1.0000x reference)
#include <cuda_runtime.h>
#include <cstdint>

#define HID 128
#define MAXN 50000
#define MAXE 640000

// ---------------- scratch (device globals; no allocation allowed) ----------------
__device__ __align__(256) float g_z[MAXN * HID];       // raw (pre-BN) layer output
__device__ __align__(256) float g_agg[MAXN * HID];     // aggregation output
__device__ __align__(256) float g_t[MAXN * HID];       // post-GEMM1 pre-BN
__device__ __align__(256) float g_stats[8 * 2 * HID];  // per-layer [sum|sumsq] slots
__device__ int g_cnt[MAXN];       // histogram (re-zeroed by scan each call)
__device__ int g_cur[MAXN];       // scatter cursor (zeroed by scan each call)
__device__ int g_rowptr[MAXN + 1];
__device__ int g_elist[MAXE];

// ---------------- f32x2 helpers ----------------
__device__ __forceinline__ unsigned long long pk2(float a) {
    unsigned long long r;
    asm("mov.b64 %0, {%1, %1};" : "=l"(r) : "f"(a));
    return r;
}
__device__ __forceinline__ void fma2(unsigned long long& d, unsigned long long a, unsigned long long b) {
    asm("fma.rn.f32x2 %0, %1, %2, %0;" : "+l"(d) : "l"(a), "l"(b));
}
__device__ __forceinline__ float2 upk(unsigned long long v) {
    float2 r;
    asm("mov.b64 {%0, %1}, %2;" : "=f"(r.x), "=f"(r.y) : "l"(v));
    return r;
}

// ================= CSR build =================
__global__ void hist_kernel(const int* __restrict__ dst, int E) {
    int i = blockIdx.x * blockDim.x + threadIdx.x;
    if (i < E) atomicAdd(&g_cnt[dst[i]], 1);
}

// scan + zero cnt/cur/stats (keeps replays deterministic without extra memsets)
__global__ void __launch_bounds__(1024) scan_kernel(int N, int E) {
    __shared__ int part[1024];
    int tid = threadIdx.x;
    int chunk = (N + 1023) / 1024;
    int base = tid * chunk;
    int s = 0;
    for (int j = 0; j < chunk; j++) {
        int idx = base + j;
        if (idx < N) s += g_cnt[idx];
    }
    part[tid] = s;
    __syncthreads();
    for (int off = 1; off < 1024; off <<= 1) {
        int v = (tid >= off) ? part[tid - off] : 0;
        __syncthreads();
        part[tid] += v;
        __syncthreads();
    }
    int run = (tid == 0) ? 0 : part[tid - 1];
    for (int j = 0; j < chunk; j++) {
        int idx = base + j;
        if (idx < N) {
            g_rowptr[idx] = run;
            run += g_cnt[idx];
            g_cnt[idx] = 0;
            g_cur[idx] = 0;
        }
    }
    if (tid == 1023) g_rowptr[N] = E;
    g_stats[tid] = 0.f;
    g_stats[tid + 1024] = 0.f;
}

__global__ void scatter_kernel(const int* __restrict__ dst, int E) {
    int i = blockIdx.x * blockDim.x + threadIdx.x;
    if (i < E) {
        int d = dst[i];
        int p = atomicAdd(&g_cur[d], 1);
        g_elist[g_rowptr[d] + p] = i;
    }
}

// ================= aggregate: warp per node, no atomics (fp32, at DRAM roofline) ====
template <bool BN>
__global__ void __launch_bounds__(256) agg_kernel(
    const float* __restrict__ z, const float* __restrict__ ea,
    const int* __restrict__ srcI, const float* __restrict__ stat_in,
    const float* __restrict__ gamma, const float* __restrict__ beta,
    float* __restrict__ agg, int N, float invN) {
    __shared__ float s_sc[HID], s_sh[HID];
    if (BN) {
        if (threadIdx.x < HID) {
            int c = threadIdx.x;
            float mu = stat_in[c] * invN;
            float var = stat_in[HID + c] * invN - mu * mu;
            float sv = gamma[c] * rsqrtf(var + 1e-5f);
            s_sc[c] = sv;
            s_sh[c] = beta[c] - sv * mu;
        }
        __syncthreads();
    }
    int warp = (blockIdx.x * blockDim.x + threadIdx.x) >> 5;
    int lane = threadIdx.x & 31;
    if (warp >= N) return;

    float4 sc, sh;
    if (BN) {
        sc = *(const float4*)&s_sc[lane * 4];
        sh = *(const float4*)&s_sh[lane * 4];
    }

    int idx = g_rowptr[warp];
    const int end = g_rowptr[warp + 1];
    float4 acc = make_float4(0.f, 0.f, 0.f, 0.f);

#define EDGE_BODY(E_, S_)                                                     \
    {                                                                         \
        float4 zv = __ldg((const float4*)(z + (size_t)(S_) * HID) + lane);    \
        float4 av = __ldcs((const float4*)(ea + (size_t)(E_) * HID) + lane);  \
        if (BN) {                                                             \
            zv.x = fmaf(sc.x, zv.x, sh.x); zv.y = fmaf(sc.y, zv.y, sh.y);     \
            zv.z = fmaf(sc.z, zv.z, sh.z); zv.w = fmaf(sc.w, zv.w, sh.w);     \
        }                                                                     \
        acc.x += fmaxf(zv.x + av.x, 0.f);                                     \
        acc.y += fmaxf(zv.y + av.y, 0.f);                                     \
        acc.z += fmaxf(zv.z + av.z, 0.f);                                     \
        acc.w += fmaxf(zv.w + av.w, 0.f);                                     \
    }

    for (; idx + 4 <= end; idx += 4) {
        int e0 = __ldg(g_elist + idx);
        int e1 = __ldg(g_elist + idx + 1);
        int e2 = __ldg(g_elist + idx + 2);
        int e3 = __ldg(g_elist + idx + 3);
        int s0 = __ldg(srcI + e0);
        int s1 = __ldg(srcI + e1);
        int s2 = __ldg(srcI + e2);
        int s3 = __ldg(srcI + e3);
        EDGE_BODY(e0, s0) EDGE_BODY(e1, s1) EDGE_BODY(e2, s2) EDGE_BODY(e3, s3)
    }
    for (; idx < end; idx++) {
        int e0 = __ldg(g_elist + idx);
        int s0 = __ldg(srcI + e0);
        EDGE_BODY(e0, s0)
    }
#undef EDGE_BODY
    ((float4*)(agg + (size_t)warp * HID))[lane] = acc;  // every row written: no memset
}

// ================= fused GEMM, transposed-A staging =================
// As_T[k][row] ([128][72] padded). A operands load pre-packed (row pairs adjacent),
// pk2 only on W (4/k/lane). Warp w: rows w*8..w*8+7; lane: cols lane*4..lane*4+3.
#define AT_PITCH 72
static const int GEMM_SMEM = (HID * HID + HID * AT_PITCH + 2 * HID) * 4;  // 103424 B

template <bool BN_IN, bool HAS_A2, bool RELU_IN, bool RELU_OUT, bool STATS>
__global__ void __launch_bounds__(256) gemm_kernel(
    const float* __restrict__ A, const float* __restrict__ A2,
    const float* __restrict__ stat_in, const float* __restrict__ gamma,
    const float* __restrict__ beta, float invN,
    const float* __restrict__ W, const float* __restrict__ bias,
    float* __restrict__ out, float* __restrict__ stat_out, int M) {
    extern __shared__ float smem[];
    float* Ws = smem;                          // [128][128]
    float* As = smem + HID * HID;              // As_T [128][AT_PITCH]
    float* s_sc = smem + HID * HID + HID * AT_PITCH;
    float* s_sh = s_sc + HID;

    const int tid = threadIdx.x;
    const int lane = tid & 31;
    const int wid = tid >> 5;
    const int row0 = blockIdx.x * 64;

    if (tid < HID) {
        if (BN_IN) {
            float mu = stat_in[tid] * invN;
            float var = stat_in[HID + tid] * invN - mu * mu;
            float sv = gamma[tid] * rsqrtf(var + 1e-5f);
            s_sc[tid] = sv;
            s_sh[tid] = beta[tid] - sv * mu;
        } else {
            s_sc[tid] = 1.f;
            s_sh[tid] = 0.f;
        }
    }

    // stage W (4096 float4)
    const float4* Wg = (const float4*)W;
    float4* Ws4 = (float4*)Ws;
#pragma unroll
    for (int i = 0; i < 16; i++) Ws4[tid + 256 * i] = __ldg(Wg + tid + 256 * i);
    __syncthreads();  // s_sc ready before staging A

    // stage A transposed: thread (r = i&63, c4 = i>>6) -> As_T[4c4+j][r]
    for (int i = tid; i < 64 * 32; i += 256) {
        int r = i & 63, c4 = i >> 6;
        int gr = row0 + r;
        float4 v = make_float4(0.f, 0.f, 0.f, 0.f);
        if (gr < M) {
            float4 zv = __ldg((const float4*)(A + (size_t)gr * HID) + c4);
            float4 s4 = *(const float4*)&s_sc[c4 * 4];
            float4 h4 = *(const float4*)&s_sh[c4 * 4];
            v.x = fmaf(s4.x, zv.x, h4.x);
            v.y = fmaf(s4.y, zv.y, h4.y);
            v.z = fmaf(s4.z, zv.z, h4.z);
            v.w = fmaf(s4.w, zv.w, h4.w);
            if (RELU_IN) {
                v.x = fmaxf(v.x, 0.f); v.y = fmaxf(v.y, 0.f);
                v.z = fmaxf(v.z, 0.f); v.w = fmaxf(v.w, 0.f);
            }
            if (HAS_A2) {
                float4 g4 = __ldg((const float4*)(A2 + (size_t)gr * HID) + c4);
                v.x += g4.x; v.y += g4.y; v.z += g4.z; v.w += g4.w;
            }
        }
        int k0 = c4 * 4;
        As[(k0 + 0) * AT_PITCH + r] = v.x;
        As[(k0 + 1) * AT_PITCH + r] = v.y;
        As[(k0 + 2) * AT_PITCH + r] = v.z;
        As[(k0 + 3) * AT_PITCH + r] = v.w;
    }
    __syncthreads();

    // acc[p*4+c]: rows (arow+2p, arow+2p+1) packed in f32x2, col cx+c
    unsigned long long acc[16];
#pragma unroll
    for (int i = 0; i < 16; i++) acc[i] = 0ull;

    const int arow = wid * 8;
    const int cx = lane * 4;
#pragma unroll 4
    for (int k = 0; k < HID; k++) {
        // A row pairs: broadcast LDS.128 (pre-packed pairs)
        ulonglong2 a01 = *(const ulonglong2*)&As[k * AT_PITCH + arow];      // pairs (0,1),(2,3)
        ulonglong2 a23 = *(const ulonglong2*)&As[k * AT_PITCH + arow + 4];  // pairs (4,5),(6,7)
        float4 wv = *(const float4*)&Ws[k * HID + cx];
        unsigned long long w0 = pk2(wv.x);
        unsigned long long w1 = pk2(wv.y);
        unsigned long long w2 = pk2(wv.z);
        unsigned long long w3 = pk2(wv.w);
        fma2(acc[0], a01.x, w0);  fma2(acc[1], a01.x, w1);
        fma2(acc[2], a01.x, w2);  fma2(acc[3], a01.x, w3);
        fma2(acc[4], a01.y, w0);  fma2(acc[5], a01.y, w1);
        fma2(acc[6], a01.y, w2);  fma2(acc[7], a01.y, w3);
        fma2(acc[8], a23.x, w0);  fma2(acc[9], a23.x, w1);
        fma2(acc[10], a23.x, w2); fma2(acc[11], a23.x, w3);
        fma2(acc[12], a23.y, w0); fma2(acc[13], a23.y, w1);
        fma2(acc[14], a23.y, w2); fma2(acc[15], a23.y, w3);
    }

    // epilogue: lane's 4 contiguous cols, 8 rows
    float bb[4];
    *(float4*)bb = __ldg((const float4*)bias + lane);
    float csum[4], csq[4];
#pragma unroll
    for (int j = 0; j < 4; j++) { csum[j] = 0.f; csq[j] = 0.f; }

#pragma unroll
    for (int p = 0; p < 4; p++) {
        float2 u0 = upk(acc[p * 4 + 0]);
        float2 u1 = upk(acc[p * 4 + 1]);
        float2 u2 = upk(acc[p * 4 + 2]);
        float2 u3 = upk(acc[p * 4 + 3]);
        int gr0 = row0 + arow + 2 * p;
        if (gr0 < M) {
            float v[4] = {u0.x + bb[0], u1.x + bb[1], u2.x + bb[2], u3.x + bb[3]};
            if (RELU_OUT) {
#pragma unroll
                for (int j = 0; j < 4; j++) v[j] = fmaxf(v[j], 0.f);
            }
            *(float4*)(out + (size_t)gr0 * HID + cx) = make_float4(v[0], v[1], v[2], v[3]);
            if (STATS) {
#pragma unroll
                for (int j = 0; j < 4; j++) { csum[j] += v[j]; csq[j] += v[j] * v[j]; }
            }
        }
        if (gr0 + 1 < M) {
            float v[4] = {u0.y + bb[0], u1.y + bb[1], u2.y + bb[2], u3.y + bb[3]};
            if (RELU_OUT) {
#pragma unroll
                for (int j = 0; j < 4; j++) v[j] = fmaxf(v[j], 0.f);
            }
            *(float4*)(out + (size_t)(gr0 + 1) * HID + cx) = make_float4(v[0], v[1], v[2], v[3]);
            if (STATS) {
#pragma unroll
                for (int j = 0; j < 4; j++) { csum[j] += v[j]; csq[j] += v[j] * v[j]; }
            }
        }
    }

    if (STATS) {
        float* red = As;  // reuse: 8 warps x 256 floats
        __syncthreads();
#pragma unroll
        for (int j = 0; j < 4; j++) {
            red[wid * 256 + lane * 4 + j] = csum[j];
            red[wid * 256 + 128 + lane * 4 + j] = csq[j];
        }
        __syncthreads();
#pragma unroll
        for (int s = 4; s > 0; s >>= 1) {
            if (wid < s) {
                for (int i = lane; i < 256; i += 32)
                    red[wid * 256 + i] += red[(wid + s) * 256 + i];
            }
            __syncthreads();
        }
        if (wid == 0) {
#pragma unroll
            for (int j = 0; j < 4; j++) {
                atomicAdd(&stat_out[lane * 4 + j], red[lane * 4 + j]);
                atomicAdd(&stat_out[HID + lane * 4 + j], red[128 + lane * 4 + j]);
            }
        }
    }
}

// ================= launcher =================
extern "C" void kernel_launch(void* const* d_in, const int* in_sizes, int n_in,
                              void* d_out, int out_size) {
    const float* x = (const float*)d_in[0];
    const int* ei = (const int*)d_in[1];   // int32 (JAX default, x64 disabled)
    const float* ea = (const float*)d_in[2];
    const float* W1 = (const float*)d_in[3];
    const float* b1 = (const float*)d_in[4];
    const float* g1 = (const float*)d_in[5];
    const float* be1 = (const float*)d_in[6];
    const float* W2 = (const float*)d_in[7];
    const float* b2 = (const float*)d_in[8];
    const float* bn_g = (const float*)d_in[9];
    const float* bn_b = (const float*)d_in[10];

    int M = in_sizes[0] / HID;
    int E = in_sizes[2] / HID;
    float* out = (float*)d_out;

    void *agg_p, *z_p, *t_p, *stats_p;
    cudaGetSymbolAddress(&agg_p, g_agg);
    cudaGetSymbolAddress(&z_p, g_z);
    cudaGetSymbolAddress(&t_p, g_t);
    cudaGetSymbolAddress(&stats_p, g_stats);
    float* stats = (float*)stats_p;

    cudaFuncSetAttribute(gemm_kernel<false, true, false, false, true>,
                         cudaFuncAttributeMaxDynamicSharedMemorySize, GEMM_SMEM);
    cudaFuncSetAttribute(gemm_kernel<true, true, false, false, true>,
                         cudaFuncAttributeMaxDynamicSharedMemorySize, GEMM_SMEM);
    cudaFuncSetAttribute(gemm_kernel<true, false, true, true, true>,
                         cudaFuncAttributeMaxDynamicSharedMemorySize, GEMM_SMEM);
    cudaFuncSetAttribute(gemm_kernel<true, false, true, true, false>,
                         cudaFuncAttributeMaxDynamicSharedMemorySize, GEMM_SMEM);

    const int* srcI = ei;
    const int* dstI = ei + E;
    int eb = (E + 255) / 256;
    int gb = (M + 63) / 64;
    int ab = (M * 32 + 255) / 256;  // warp per node
    float invN = 1.0f / (float)M;

    // CSR build (scan also zeroes stats/cnt/cur for graph replays)
    hist_kernel<<<eb, 256>>>(dstI, E);
    scan_kernel<<<1, 1024>>>(M, E);
    scatter_kernel<<<eb, 256>>>(dstI, E);

    for (int i = 0; i < 4; i++) {
        const float* zsrc = (i == 0) ? x : (const float*)z_p;
        float* stat_t = stats + (size_t)(2 * i) * 2 * HID;
        float* stat_z = stats + (size_t)(2 * i + 1) * 2 * HID;
        float* stat_z_prev = stats + (size_t)(2 * i - 1) * 2 * HID;

        if (i == 0)
            agg_kernel<false><<<ab, 256>>>(zsrc, ea, srcI, nullptr, nullptr, nullptr,
                                           (float*)agg_p, M, invN);
        else
            agg_kernel<true><<<ab, 256>>>(zsrc, ea, srcI, stat_z_prev,
                                          bn_g + (size_t)(i - 1) * HID,
                                          bn_b + (size_t)(i - 1) * HID,
                                          (float*)agg_p, M, invN);

        if (i == 0)
            gemm_kernel<false, true, false, false, true><<<gb, 256, GEMM_SMEM>>>(
                zsrc, (const float*)agg_p, nullptr, nullptr, nullptr, invN,
                W1, b1, (float*)t_p, stat_t, M);
        else
            gemm_kernel<true, true, false, false, true><<<gb, 256, GEMM_SMEM>>>(
                zsrc, (const float*)agg_p, stat_z_prev,
                bn_g + (size_t)(i - 1) * HID, bn_b + (size_t)(i - 1) * HID, invN,
                W1 + (size_t)i * HID * HID, b1 + (size_t)i * HID,
                (float*)t_p, stat_t, M);

        if (i < 3)
            gemm_kernel<true, false, true, true, true><<<gb, 256, GEMM_SMEM>>>(
                (const float*)t_p, nullptr, stat_t,
                g1 + (size_t)i * HID, be1 + (size_t)i * HID, invN,
                W2 + (size_t)i * HID * HID, b2 + (size_t)i * HID,
                (float*)z_p, stat_z, M);
        else
            gemm_kernel<true, false, true, true, false><<<gb, 256, GEMM_SMEM>>>(
                (const float*)t_p, nullptr, stat_t,
                g1 + (size_t)i * HID, be1 + (size_t)i * HID, invN,
                W2 + (size_t)i * HID * HID, b2 + (size_t)i * HID,
                out, nullptr, M);
    }
}